// round 3
// baseline (speedup 1.0000x reference)
#include <cuda_runtime.h>
#include <math.h>

// ---------------- problem constants ----------------
#define Bn   256
#define Tn   512
#define INn  32
#define Hn   128
#define Sn   4
#define HQn  32
#define BTn  (Bn*Tn)          // 131072 positions
#define DTC  0.1f
#define LOG2E 1.4426950408889634f

typedef unsigned long long u64;

// ---------------- scratch (static device globals; no allocation) ----------------
__device__ float g_xp  [(size_t)BTn*Hn];        //  64 MB  x @ Wp.T + bp
__device__ float g_inp [(size_t)Sn*BTn*Hn];     // 268 MB  per-scale input drive (incl. biases)
__device__ float g_itau[(size_t)Sn*BTn*Hn];     // 268 MB  per-scale 1/tau
__device__ float g_hT  [Sn*Bn*Hn];              // final hidden states

// ---------------- packed fp32x2 helpers (Blackwell FFMA2) ----------------
__device__ __forceinline__ void ffma2(u64 &d, u64 a, u64 b) {
    asm("fma.rn.f32x2 %0, %1, %2, %0;" : "+l"(d) : "l"(a), "l"(b));
}
__device__ __forceinline__ void add2(u64 &d, u64 a) {
    asm("add.rn.f32x2 %0, %0, %1;" : "+l"(d) : "l"(a));
}
__device__ __forceinline__ float hsum1(u64 a0) {
    float x0, y0;
    asm("mov.b64 {%0,%1}, %2;" : "=f"(x0), "=f"(y0) : "l"(a0));
    return x0 + y0;
}
__device__ __forceinline__ float hsum4(u64 a0, u64 a1, u64 a2, u64 a3) {
    add2(a0, a1); add2(a2, a3); add2(a0, a2);
    return hsum1(a0);
}

// ---------------- fast approx math ----------------
__device__ __forceinline__ float fast_ex2(float x) {
    float r; asm("ex2.approx.f32 %0, %1;" : "=f"(r) : "f"(x)); return r;
}
__device__ __forceinline__ float fast_rcp(float x) {
    float r; asm("rcp.approx.f32 %0, %1;" : "=f"(r) : "f"(x)); return r;
}
__device__ __forceinline__ float fast_sqrt(float x) {
    float r; asm("sqrt.approx.f32 %0, %1;" : "=f"(r) : "f"(x)); return r;
}
// tanh(x) = 1 - 2/(e^{2x}+1), via ex2.approx + rcp.approx (~1e-6 rel err)
__device__ __forceinline__ float fast_tanh(float x) {
    float xc = fminf(fmaxf(x, -12.f), 12.f);
    float e  = fast_ex2(xc * (2.f * LOG2E));
    return 1.f - 2.f * fast_rcp(e + 1.f);
}
// sigmoid(z) = 1/(1+2^{-z*log2e})
__device__ __forceinline__ float fast_sigmoid(float z) {
    float zc = fminf(fmaxf(z, -30.f), 30.f);
    return fast_rcp(1.f + fast_ex2(-zc * LOG2E));
}

// ============================================================================
// K1: x_proj[pos, i] = x[pos, :32] @ Wp[i, :32] + bp[i]
// ============================================================================
__global__ void __launch_bounds__(128) k_xp(const float* __restrict__ x,
                                            const float* __restrict__ Wp,
                                            const float* __restrict__ bp) {
    const int i  = threadIdx.x;
    const int p0 = blockIdx.x * 32;
    __shared__ float xs[32][INn];

    const float4* src = (const float4*)(x + (size_t)p0 * INn);
    float4* dst = (float4*)&xs[0][0];
    dst[i]       = src[i];
    dst[i + 128] = src[i + 128];

    u64 w[16];
    const u64* wq = (const u64*)(Wp + (size_t)i * INn);
#pragma unroll
    for (int m = 0; m < 16; m++) w[m] = wq[m];
    const float bias = bp[i];
    __syncthreads();

#pragma unroll 4
    for (int p = 0; p < 32; p++) {
        const u64* xq = (const u64*)&xs[p][0];
        u64 a0 = 0ull, a1 = 0ull, a2 = 0ull, a3 = 0ull;
#pragma unroll
        for (int m = 0; m < 16; m += 4) {
            ffma2(a0, w[m], xq[m]);   ffma2(a1, w[m+1], xq[m+1]);
            ffma2(a2, w[m+2], xq[m+2]); ffma2(a3, w[m+3], xq[m+3]);
        }
        g_xp[(size_t)(p0 + p) * Hn + i] = hsum4(a0, a1, a2, a3) + bias;
    }
}

// ============================================================================
// K2: inp[s,pos,i] = xp[pos,:] @ Win_w[s,i,:] + Win_b[s,i] + cbias[s,i]
// ============================================================================
__global__ void __launch_bounds__(128) k_inp(const float* __restrict__ Win_w,
                                             const float* __restrict__ Win_b,
                                             const float* __restrict__ cbias) {
    const int i  = threadIdx.x;
    const int s  = blockIdx.y;
    const int p0 = blockIdx.x * 32;
    __shared__ float xs[32][Hn];

    const float4* src = (const float4*)(g_xp + (size_t)p0 * Hn);
    float4* dst = (float4*)&xs[0][0];
#pragma unroll
    for (int r = i; r < 1024; r += 128) dst[r] = src[r];

    u64 w[64];
    const u64* wq = (const u64*)(Win_w + ((size_t)s * Hn + i) * Hn);
#pragma unroll
    for (int m = 0; m < 64; m++) w[m] = wq[m];
    const float bias = Win_b[s * Hn + i] + cbias[s * Hn + i];
    __syncthreads();

    float* outp = g_inp + ((size_t)s * BTn + p0) * Hn + i;
#pragma unroll 2
    for (int p = 0; p < 32; p++) {
        const u64* xq = (const u64*)&xs[p][0];
        u64 a0 = 0ull, a1 = 0ull, a2 = 0ull, a3 = 0ull;
#pragma unroll
        for (int m = 0; m < 64; m += 4) {
            ffma2(a0, w[m], xq[m]);     ffma2(a1, w[m+1], xq[m+1]);
            ffma2(a2, w[m+2], xq[m+2]); ffma2(a3, w[m+3], xq[m+3]);
        }
        __stwt(outp + (size_t)p * Hn, hsum4(a0, a1, a2, a3) + bias);
    }
}

// ============================================================================
// K3: volatility gate -> itau[s,pos,i]
// ============================================================================
__global__ void __launch_bounds__(128) k_itau(const float* __restrict__ v1w,
                                              const float* __restrict__ v1b,
                                              const float* __restrict__ v2w,
                                              const float* __restrict__ v2b,
                                              const float* __restrict__ tau_base) {
    const int i  = threadIdx.x;
    const int s  = blockIdx.y;
    const int p0 = blockIdx.x * 32;
    __shared__ float xs[32][Hn];
    __shared__ float gs[32][HQn];

    const float4* src = (const float4*)(g_xp + (size_t)p0 * Hn);
    float4* dst = (float4*)&xs[0][0];
#pragma unroll
    for (int r = i; r < 1024; r += 128) dst[r] = src[r];
    __syncthreads();

    // ---- stage 1: g = relu(xp @ v1w.T + v1b) ----
    {
        const int q   = i & 31;
        const int grp = i >> 5;
        u64 wv[64];
        const u64* wq = (const u64*)(v1w + ((size_t)s * HQn + q) * Hn);
#pragma unroll
        for (int m = 0; m < 64; m++) wv[m] = wq[m];
        const float b1 = v1b[s * HQn + q];
#pragma unroll 2
        for (int pp = 0; pp < 8; pp++) {
            const int p = grp * 8 + pp;
            const u64* xq = (const u64*)&xs[p][0];
            u64 a0 = 0ull, a1 = 0ull, a2 = 0ull, a3 = 0ull;
#pragma unroll
            for (int m = 0; m < 64; m += 4) {
                ffma2(a0, wv[m], xq[m]);     ffma2(a1, wv[m+1], xq[m+1]);
                ffma2(a2, wv[m+2], xq[m+2]); ffma2(a3, wv[m+3], xq[m+3]);
            }
            gs[p][q] = fmaxf(hsum4(a0, a1, a2, a3) + b1, 0.f);
        }
    }
    __syncthreads();

    // ---- stage 2: vol -> itau ----
    {
        u64 w2[16];
        const u64* wq = (const u64*)(v2w + ((size_t)s * Hn + i) * HQn);
#pragma unroll
        for (int m = 0; m < 16; m++) w2[m] = wq[m];
        const float b2 = v2b[s * Hn + i];
        const float tb = tau_base[s * Hn + i];
        float* outp = g_itau + ((size_t)s * BTn + p0) * Hn + i;
#pragma unroll 2
        for (int p = 0; p < 32; p++) {
            const u64* gq = (const u64*)&gs[p][0];
            u64 a0 = 0ull, a1 = 0ull, a2 = 0ull, a3 = 0ull;
#pragma unroll
            for (int m = 0; m < 16; m += 4) {
                ffma2(a0, w2[m], gq[m]);     ffma2(a1, w2[m+1], gq[m+1]);
                ffma2(a2, w2[m+2], gq[m+2]); ffma2(a3, w2[m+3], gq[m+3]);
            }
            const float z   = hsum4(a0, a1, a2, a3) + b2;
            const float vol = fast_sigmoid(z);
            float tau = tb * (0.2f + 1.8f * (1.f - vol));
            tau = fminf(fmaxf(tau, 0.1f), 10.f);
            __stwt(outp + (size_t)p * Hn, 1.f / tau);
        }
    }
}

// ============================================================================
// K4: liquid-cell scan, split-K version.
// 256 threads per CTA; thread t owns (channel c = t>>1, half = t&1).
// Each thread holds HALF of Wrec row c (64 floats = 32 packed pairs) in regs.
// Partner lanes (adjacent, shfl_xor 1) combine partial dots -> both lanes of
// a channel hold identical dh; warp norm reduction then needs only offsets
// {2,4,8,16} (sums 16 distinct channels exactly once).
// Heavy scales (s=3, 9 inner steps) launched first for LPT wave balance.
// ============================================================================
__global__ void __launch_bounds__(256, 2) k_scan(const float* __restrict__ Wrec) {
    const int bid  = blockIdx.x;
    const int s    = 3 - (bid >> 8);     // s=3 scheduled first
    const int b    = bid & 255;
    const int t    = threadIdx.x;
    const int c    = t >> 1;
    const int half = t & 1;
    const int lane = t & 31;
    const int wid  = t >> 5;             // 0..7

    __shared__ float h_s[Hn];
    __shared__ __align__(16) float red[8];

    // half-row of Wrec in registers
    u64 w[32];
    const u64* wq = (const u64*)(Wrec + ((size_t)s * Hn + c) * Hn + half * 64);
#pragma unroll
    for (int m = 0; m < 32; m++) w[m] = wq[m];

    if (half == 0) h_s[c] = 0.f;
    float h = 0.f;
    const int nsteps = 3 + 2 * s;
    const float* inp_ptr  = g_inp  + ((size_t)(s * Bn + b)) * Tn * Hn + c;
    const float* itau_ptr = g_itau + ((size_t)(s * Bn + b)) * Tn * Hn + c;
    __syncthreads();

    float inp  = __ldcs(inp_ptr);
    float itau = __ldcs(itau_ptr);
    for (int tt = 0; tt < Tn; tt++) {
        const int tn = (tt + 1 < Tn) ? tt + 1 : tt;
        const float ninp  = __ldcs(inp_ptr  + (size_t)tn * Hn);
        const float nitau = __ldcs(itau_ptr + (size_t)tn * Hn);

        for (int k = 0; k < nsteps; k++) {
            // partial dot: this thread's 64 h-elements
            const u64* hq = (const u64*)h_s + half * 32;
            u64 a0 = 0ull, a1 = 0ull, a2 = 0ull, a3 = 0ull;
#pragma unroll
            for (int m = 0; m < 32; m += 4) {
                ffma2(a0, w[m], hq[m]);     ffma2(a1, w[m+1], hq[m+1]);
                ffma2(a2, w[m+2], hq[m+2]); ffma2(a3, w[m+3], hq[m+3]);
            }
            float part = hsum4(a0, a1, a2, a3);
            const float z = part + __shfl_xor_sync(0xffffffffu, part, 1) + inp;

            const float target = fast_tanh(z);
            const float dh = (target - h) * itau;

            // ||dhdt||^2: lanes 2c/2c+1 duplicate dh, so offsets {2,4,8,16}
            // give the 16-distinct-channel sum per warp.
            float sq = dh * dh;
            sq += __shfl_xor_sync(0xffffffffu, sq, 2);
            sq += __shfl_xor_sync(0xffffffffu, sq, 4);
            sq += __shfl_xor_sync(0xffffffffu, sq, 8);
            sq += __shfl_xor_sync(0xffffffffu, sq, 16);
            if (lane == 0) red[wid] = sq;
            __syncthreads();
            const float4 r0 = *(const float4*)red;
            const float4 r1 = *(const float4*)(red + 4);
            const float tot = ((r0.x + r0.y) + (r0.z + r0.w)) +
                              ((r1.x + r1.y) + (r1.z + r1.w));
            const float mag = fast_sqrt(tot);
            const float sc  = DTC * fast_rcp(fmaf(0.2f, mag, 1.f));
            h = fmaf(sc, dh, h);
            if (half == 0) h_s[c] = h;
            __syncthreads();
        }
        inp = ninp; itau = nitau;
    }
    if (half == 0) g_hT[((size_t)(s * Bn + b)) * Hn + c] = h;
}

// ============================================================================
// K5: projection heads + fusion MLP. One CTA per batch row.
// ============================================================================
__global__ void __launch_bounds__(128) k_head(const float* __restrict__ proj_w,
                                              const float* __restrict__ proj_b,
                                              const float* __restrict__ f1_w,
                                              const float* __restrict__ f1_b,
                                              const float* __restrict__ f2_w,
                                              const float* __restrict__ f2_b,
                                              const float* __restrict__ f3_w,
                                              const float* __restrict__ f3_b,
                                              float* __restrict__ out) {
    const int b = blockIdx.x;
    const int i = threadIdx.x;
    __shared__ float fs[Hn];
    __shared__ float h1s[Hn];
    __shared__ float h2s[64];
    __shared__ float rs[4];

    {
        const int s = i >> 5, q = i & 31;
        const float* hrow = g_hT + (size_t)(s * Bn + b) * Hn;
        const float* pw   = proj_w + (size_t)(s * 32 + q) * Hn;
        float acc = proj_b[s * 32 + q];
#pragma unroll 8
        for (int j = 0; j < Hn; j++) acc += hrow[j] * pw[j];
        fs[i] = acc;
    }
    __syncthreads();

    {
        const float* w1 = f1_w + (size_t)i * Hn;
        float acc = f1_b[i];
#pragma unroll 8
        for (int j = 0; j < Hn; j++) acc += fs[j] * w1[j];
        h1s[i] = fmaxf(acc, 0.f);
    }
    __syncthreads();

    if (i < 64) {
        const float* w2 = f2_w + (size_t)i * Hn;
        float acc = f2_b[i];
#pragma unroll 8
        for (int j = 0; j < Hn; j++) acc += h1s[j] * w2[j];
        h2s[i] = fmaxf(acc, 0.f);
    }
    __syncthreads();

    float pr = (i < 64) ? h2s[i] * f3_w[i] : 0.f;
#pragma unroll
    for (int off = 16; off; off >>= 1) pr += __shfl_xor_sync(0xffffffffu, pr, off);
    if ((i & 31) == 0) rs[i >> 5] = pr;
    __syncthreads();
    if (i == 0) out[b] = rs[0] + rs[1] + f3_b[0];
}

// ============================================================================
extern "C" void kernel_launch(void* const* d_in, const int* in_sizes, int n_in,
                              void* d_out, int out_size) {
    (void)in_sizes; (void)n_in; (void)out_size;
    const float* x        = (const float*)d_in[0];
    const float* Wp       = (const float*)d_in[1];
    const float* bp       = (const float*)d_in[2];
    const float* Wrec     = (const float*)d_in[3];
    const float* Win_w    = (const float*)d_in[4];
    const float* Win_b    = (const float*)d_in[5];
    const float* cbias    = (const float*)d_in[6];
    const float* tau_base = (const float*)d_in[7];
    const float* vg1_w    = (const float*)d_in[8];
    const float* vg1_b    = (const float*)d_in[9];
    const float* vg2_w    = (const float*)d_in[10];
    const float* vg2_b    = (const float*)d_in[11];
    const float* proj_w   = (const float*)d_in[12];
    const float* proj_b   = (const float*)d_in[13];
    const float* f1_w     = (const float*)d_in[14];
    const float* f1_b     = (const float*)d_in[15];
    const float* f2_w     = (const float*)d_in[16];
    const float* f2_b     = (const float*)d_in[17];
    const float* f3_w     = (const float*)d_in[18];
    const float* f3_b     = (const float*)d_in[19];
    float* out = (float*)d_out;

    k_xp  <<<BTn / 32, 128>>>(x, Wp, bp);
    k_inp <<<dim3(BTn / 32, Sn), 128>>>(Win_w, Win_b, cbias);
    k_itau<<<dim3(BTn / 32, Sn), 128>>>(vg1_w, vg1_b, vg2_w, vg2_b, tau_base);
    k_scan<<<Sn * Bn, 256>>>(Wrec);
    k_head<<<Bn, 128>>>(proj_w, proj_b, f1_w, f1_b, f2_w, f2_b, f3_w, f3_b, out);
}

// round 4
// speedup vs baseline: 1.6869x; 1.6869x over previous
#include <cuda_runtime.h>
#include <math.h>

// ---------------- problem constants ----------------
#define Bn   256
#define Tn   512
#define INn  32
#define Hn   128
#define Sn   4
#define HQn  32
#define BTn  (Bn*Tn)          // 131072 positions
#define DTC  0.1f
#define LOG2E 1.4426950408889634f

typedef unsigned long long u64;
typedef ulonglong2 u64x2;

// ---------------- scratch (static device globals; no allocation) ----------------
__device__ float g_xp  [(size_t)BTn*Hn];        //  64 MB
__device__ float g_inp [(size_t)Sn*BTn*Hn];     // 268 MB
__device__ float g_itau[(size_t)Sn*BTn*Hn];     // 268 MB
__device__ float g_hT  [Sn*Bn*Hn];

// ---------------- packed fp32x2 helpers (Blackwell FFMA2) ----------------
__device__ __forceinline__ void ffma2(u64 &d, u64 a, u64 b) {
    asm("fma.rn.f32x2 %0, %1, %2, %0;" : "+l"(d) : "l"(a), "l"(b));
}
__device__ __forceinline__ void add2(u64 &d, u64 a) {
    asm("add.rn.f32x2 %0, %0, %1;" : "+l"(d) : "l"(a));
}
__device__ __forceinline__ float hsum1(u64 a0) {
    float x0, y0;
    asm("mov.b64 {%0,%1}, %2;" : "=f"(x0), "=f"(y0) : "l"(a0));
    return x0 + y0;
}
__device__ __forceinline__ float hsum4(u64 a0, u64 a1, u64 a2, u64 a3) {
    add2(a0, a1); add2(a2, a3); add2(a0, a2);
    return hsum1(a0);
}

// ---------------- fast approx math ----------------
__device__ __forceinline__ float fast_ex2(float x) {
    float r; asm("ex2.approx.f32 %0, %1;" : "=f"(r) : "f"(x)); return r;
}
__device__ __forceinline__ float fast_rcp(float x) {
    float r; asm("rcp.approx.f32 %0, %1;" : "=f"(r) : "f"(x)); return r;
}
__device__ __forceinline__ float fast_sqrt(float x) {
    float r; asm("sqrt.approx.f32 %0, %1;" : "=f"(r) : "f"(x)); return r;
}
// tanh(x) = 1 - 2/(e^{2x}+1)
__device__ __forceinline__ float fast_tanh(float x) {
    float xc = fminf(fmaxf(x, -12.f), 12.f);
    float e  = fast_ex2(xc * (2.f * LOG2E));
    return 1.f - 2.f * fast_rcp(e + 1.f);
}
__device__ __forceinline__ float fast_sigmoid(float z) {
    float zc = fminf(fmaxf(z, -30.f), 30.f);
    return fast_rcp(1.f + fast_ex2(-zc * LOG2E));
}

// ============================================================================
// K1: x_proj[pos, i] = x[pos, :32] @ Wp[i, :32] + bp[i]
// ============================================================================
__global__ void __launch_bounds__(128) k_xp(const float* __restrict__ x,
                                            const float* __restrict__ Wp,
                                            const float* __restrict__ bp) {
    const int i  = threadIdx.x;
    const int p0 = blockIdx.x * 32;
    __shared__ __align__(16) float xs[32][INn];

    const float4* src = (const float4*)(x + (size_t)p0 * INn);
    float4* dst = (float4*)&xs[0][0];
    dst[i]       = src[i];
    dst[i + 128] = src[i + 128];

    u64 w[16];
    {
        const u64x2* wq = (const u64x2*)(Wp + (size_t)i * INn);
#pragma unroll
        for (int m = 0; m < 8; m++) { u64x2 v = wq[m]; w[2*m] = v.x; w[2*m+1] = v.y; }
    }
    const float bias = bp[i];
    __syncthreads();

#pragma unroll 4
    for (int p = 0; p < 32; p++) {
        const u64x2* xq = (const u64x2*)&xs[p][0];
        u64 a0 = 0ull, a1 = 0ull, a2 = 0ull, a3 = 0ull;
#pragma unroll
        for (int m = 0; m < 8; m += 2) {
            u64x2 p0v = xq[m], p1v = xq[m+1];
            ffma2(a0, w[2*m],   p0v.x); ffma2(a1, w[2*m+1], p0v.y);
            ffma2(a2, w[2*m+2], p1v.x); ffma2(a3, w[2*m+3], p1v.y);
        }
        g_xp[(size_t)(p0 + p) * Hn + i] = hsum4(a0, a1, a2, a3) + bias;
    }
}

// ============================================================================
// K2: inp[s,pos,i] = xp[pos,:] @ Win_w[s,i,:] + Win_b[s,i] + cbias[s,i]
// ============================================================================
__global__ void __launch_bounds__(128) k_inp(const float* __restrict__ Win_w,
                                             const float* __restrict__ Win_b,
                                             const float* __restrict__ cbias) {
    const int i  = threadIdx.x;
    const int s  = blockIdx.y;
    const int p0 = blockIdx.x * 32;
    __shared__ __align__(16) float xs[32][Hn];

    const float4* src = (const float4*)(g_xp + (size_t)p0 * Hn);
    float4* dst = (float4*)&xs[0][0];
#pragma unroll
    for (int r = i; r < 1024; r += 128) dst[r] = src[r];

    u64 w[64];
    {
        const u64x2* wq = (const u64x2*)(Win_w + ((size_t)s * Hn + i) * Hn);
#pragma unroll
        for (int m = 0; m < 32; m++) { u64x2 v = wq[m]; w[2*m] = v.x; w[2*m+1] = v.y; }
    }
    const float bias = Win_b[s * Hn + i] + cbias[s * Hn + i];
    __syncthreads();

    float* outp = g_inp + ((size_t)s * BTn + p0) * Hn + i;
#pragma unroll 2
    for (int p = 0; p < 32; p++) {
        const u64x2* xq = (const u64x2*)&xs[p][0];
        u64 a0 = 0ull, a1 = 0ull, a2 = 0ull, a3 = 0ull;
#pragma unroll
        for (int m = 0; m < 32; m += 2) {
            u64x2 p0v = xq[m], p1v = xq[m+1];
            ffma2(a0, w[2*m],   p0v.x); ffma2(a1, w[2*m+1], p0v.y);
            ffma2(a2, w[2*m+2], p1v.x); ffma2(a3, w[2*m+3], p1v.y);
        }
        __stwt(outp + (size_t)p * Hn, hsum4(a0, a1, a2, a3) + bias);
    }
}

// ============================================================================
// K3: volatility gate -> itau[s,pos,i]
// ============================================================================
__global__ void __launch_bounds__(128) k_itau(const float* __restrict__ v1w,
                                              const float* __restrict__ v1b,
                                              const float* __restrict__ v2w,
                                              const float* __restrict__ v2b,
                                              const float* __restrict__ tau_base) {
    const int i  = threadIdx.x;
    const int s  = blockIdx.y;
    const int p0 = blockIdx.x * 32;
    __shared__ __align__(16) float xs[32][Hn];
    __shared__ __align__(16) float gs[32][HQn];

    const float4* src = (const float4*)(g_xp + (size_t)p0 * Hn);
    float4* dst = (float4*)&xs[0][0];
#pragma unroll
    for (int r = i; r < 1024; r += 128) dst[r] = src[r];
    __syncthreads();

    // ---- stage 1: g = relu(xp @ v1w.T + v1b) ----
    {
        const int q   = i & 31;
        const int grp = i >> 5;
        u64 wv[64];
        const u64x2* wq = (const u64x2*)(v1w + ((size_t)s * HQn + q) * Hn);
#pragma unroll
        for (int m = 0; m < 32; m++) { u64x2 v = wq[m]; wv[2*m] = v.x; wv[2*m+1] = v.y; }
        const float b1 = v1b[s * HQn + q];
#pragma unroll 2
        for (int pp = 0; pp < 8; pp++) {
            const int p = grp * 8 + pp;
            const u64x2* xq = (const u64x2*)&xs[p][0];
            u64 a0 = 0ull, a1 = 0ull, a2 = 0ull, a3 = 0ull;
#pragma unroll
            for (int m = 0; m < 32; m += 2) {
                u64x2 p0v = xq[m], p1v = xq[m+1];
                ffma2(a0, wv[2*m],   p0v.x); ffma2(a1, wv[2*m+1], p0v.y);
                ffma2(a2, wv[2*m+2], p1v.x); ffma2(a3, wv[2*m+3], p1v.y);
            }
            gs[p][q] = fmaxf(hsum4(a0, a1, a2, a3) + b1, 0.f);
        }
    }
    __syncthreads();

    // ---- stage 2: vol -> itau ----
    {
        u64 w2[16];
        const u64x2* wq = (const u64x2*)(v2w + ((size_t)s * Hn + i) * HQn);
#pragma unroll
        for (int m = 0; m < 8; m++) { u64x2 v = wq[m]; w2[2*m] = v.x; w2[2*m+1] = v.y; }
        const float b2 = v2b[s * Hn + i];
        const float tb = tau_base[s * Hn + i];
        float* outp = g_itau + ((size_t)s * BTn + p0) * Hn + i;
#pragma unroll 2
        for (int p = 0; p < 32; p++) {
            const u64x2* gq = (const u64x2*)&gs[p][0];
            u64 a0 = 0ull, a1 = 0ull, a2 = 0ull, a3 = 0ull;
#pragma unroll
            for (int m = 0; m < 8; m += 2) {
                u64x2 p0v = gq[m], p1v = gq[m+1];
                ffma2(a0, w2[2*m],   p0v.x); ffma2(a1, w2[2*m+1], p0v.y);
                ffma2(a2, w2[2*m+2], p1v.x); ffma2(a3, w2[2*m+3], p1v.y);
            }
            const float z   = hsum4(a0, a1, a2, a3) + b2;
            const float vol = fast_sigmoid(z);
            float tau = tb * (0.2f + 1.8f * (1.f - vol));
            tau = fminf(fmaxf(tau, 0.1f), 10.f);
            __stwt(outp + (size_t)p * Hn, 1.f / tau);
        }
    }
}

// ============================================================================
// K4: liquid-cell scan. 128 threads/CTA; thread i = channel i.
// Full Wrec row (128 f32 = 64 packed pairs) in registers.
// h broadcast from smem via LDS.128 (32 loads/step, conflict-free broadcast).
// Approx tanh/sqrt/rcp; LPT (s=3 first); __ldcs prefetch of next drive.
// ============================================================================
__global__ void __launch_bounds__(128, 3) k_scan(const float* __restrict__ Wrec) {
    const int bid  = blockIdx.x;
    const int s    = 3 - (bid >> 8);     // heavy scale first (LPT)
    const int b    = bid & 255;
    const int i    = threadIdx.x;
    const int lane = i & 31, wid = i >> 5;

    __shared__ __align__(16) float h_s[Hn];
    __shared__ __align__(16) float red[4];

    // full row of Wrec in registers (LDG.128)
    u64 w[64];
    {
        const u64x2* wq = (const u64x2*)(Wrec + ((size_t)s * Hn + i) * Hn);
#pragma unroll
        for (int m = 0; m < 32; m++) { u64x2 v = wq[m]; w[2*m] = v.x; w[2*m+1] = v.y; }
    }

    float h = 0.f;
    h_s[i] = 0.f;
    const int nsteps = 3 + 2 * s;
    const float* inp_ptr  = g_inp  + ((size_t)(s * Bn + b)) * Tn * Hn + i;
    const float* itau_ptr = g_itau + ((size_t)(s * Bn + b)) * Tn * Hn + i;
    __syncthreads();

    float inp  = __ldcs(inp_ptr);
    float itau = __ldcs(itau_ptr);
    for (int tt = 0; tt < Tn; tt++) {
        const int tn = (tt + 1 < Tn) ? tt + 1 : tt;
        const float ninp  = __ldcs(inp_ptr  + (size_t)tn * Hn);
        const float nitau = __ldcs(itau_ptr + (size_t)tn * Hn);

        for (int k = 0; k < nsteps; k++) {
            // target_i = tanh( W[i,:] . h + inp_i )   -- 32x LDS.128 broadcast
            const u64x2* hq = (const u64x2*)h_s;
            u64 a0 = 0ull, a1 = 0ull, a2 = 0ull, a3 = 0ull;
#pragma unroll
            for (int m = 0; m < 32; m += 2) {
                u64x2 p0v = hq[m], p1v = hq[m+1];
                ffma2(a0, w[2*m],   p0v.x); ffma2(a1, w[2*m+1], p0v.y);
                ffma2(a2, w[2*m+2], p1v.x); ffma2(a3, w[2*m+3], p1v.y);
            }
            const float target = fast_tanh(hsum4(a0, a1, a2, a3) + inp);
            const float dh = (target - h) * itau;

            // ||dhdt|| over 128 channels
            float sq = dh * dh;
#pragma unroll
            for (int off = 16; off; off >>= 1) sq += __shfl_xor_sync(0xffffffffu, sq, off);
            if (lane == 0) red[wid] = sq;
            __syncthreads();
            const float4 r = *(const float4*)red;
            const float mag = fast_sqrt((r.x + r.y) + (r.z + r.w));
            const float sc  = DTC * fast_rcp(fmaf(0.2f, mag, 1.f));
            h = fmaf(sc, dh, h);
            h_s[i] = h;
            __syncthreads();
        }
        inp = ninp; itau = nitau;
    }
    g_hT[((size_t)(s * Bn + b)) * Hn + i] = h;
}

// ============================================================================
// K5: projection heads + fusion MLP. One CTA per batch row.
// ============================================================================
__global__ void __launch_bounds__(128) k_head(const float* __restrict__ proj_w,
                                              const float* __restrict__ proj_b,
                                              const float* __restrict__ f1_w,
                                              const float* __restrict__ f1_b,
                                              const float* __restrict__ f2_w,
                                              const float* __restrict__ f2_b,
                                              const float* __restrict__ f3_w,
                                              const float* __restrict__ f3_b,
                                              float* __restrict__ out) {
    const int b = blockIdx.x;
    const int i = threadIdx.x;
    __shared__ float fs[Hn];
    __shared__ float h1s[Hn];
    __shared__ float h2s[64];
    __shared__ float rs[4];

    {
        const int s = i >> 5, q = i & 31;
        const float* hrow = g_hT + (size_t)(s * Bn + b) * Hn;
        const float* pw   = proj_w + (size_t)(s * 32 + q) * Hn;
        float acc = proj_b[s * 32 + q];
#pragma unroll 8
        for (int j = 0; j < Hn; j++) acc += hrow[j] * pw[j];
        fs[i] = acc;
    }
    __syncthreads();

    {
        const float* w1 = f1_w + (size_t)i * Hn;
        float acc = f1_b[i];
#pragma unroll 8
        for (int j = 0; j < Hn; j++) acc += fs[j] * w1[j];
        h1s[i] = fmaxf(acc, 0.f);
    }
    __syncthreads();

    if (i < 64) {
        const float* w2 = f2_w + (size_t)i * Hn;
        float acc = f2_b[i];
#pragma unroll 8
        for (int j = 0; j < Hn; j++) acc += h1s[j] * w2[j];
        h2s[i] = fmaxf(acc, 0.f);
    }
    __syncthreads();

    float pr = (i < 64) ? h2s[i] * f3_w[i] : 0.f;
#pragma unroll
    for (int off = 16; off; off >>= 1) pr += __shfl_xor_sync(0xffffffffu, pr, off);
    if ((i & 31) == 0) rs[i >> 5] = pr;
    __syncthreads();
    if (i == 0) out[b] = rs[0] + rs[1] + f3_b[0];
}

// ============================================================================
extern "C" void kernel_launch(void* const* d_in, const int* in_sizes, int n_in,
                              void* d_out, int out_size) {
    (void)in_sizes; (void)n_in; (void)out_size;
    const float* x        = (const float*)d_in[0];
    const float* Wp       = (const float*)d_in[1];
    const float* bp       = (const float*)d_in[2];
    const float* Wrec     = (const float*)d_in[3];
    const float* Win_w    = (const float*)d_in[4];
    const float* Win_b    = (const float*)d_in[5];
    const float* cbias    = (const float*)d_in[6];
    const float* tau_base = (const float*)d_in[7];
    const float* vg1_w    = (const float*)d_in[8];
    const float* vg1_b    = (const float*)d_in[9];
    const float* vg2_w    = (const float*)d_in[10];
    const float* vg2_b    = (const float*)d_in[11];
    const float* proj_w   = (const float*)d_in[12];
    const float* proj_b   = (const float*)d_in[13];
    const float* f1_w     = (const float*)d_in[14];
    const float* f1_b     = (const float*)d_in[15];
    const float* f2_w     = (const float*)d_in[16];
    const float* f2_b     = (const float*)d_in[17];
    const float* f3_w     = (const float*)d_in[18];
    const float* f3_b     = (const float*)d_in[19];
    float* out = (float*)d_out;

    k_xp  <<<BTn / 32, 128>>>(x, Wp, bp);
    k_inp <<<dim3(BTn / 32, Sn), 128>>>(Win_w, Win_b, cbias);
    k_itau<<<dim3(BTn / 32, Sn), 128>>>(vg1_w, vg1_b, vg2_w, vg2_b, tau_base);
    k_scan<<<Sn * Bn, 128>>>(Wrec);
    k_head<<<Bn, 128>>>(proj_w, proj_b, f1_w, f1_b, f2_w, f2_b, f3_w, f3_b, out);
}

// round 5
// speedup vs baseline: 1.8030x; 1.0688x over previous
#include <cuda_runtime.h>
#include <math.h>

// ---------------- problem constants ----------------
#define Bn   256
#define Tn   512
#define INn  32
#define Hn   128
#define Sn   4
#define HQn  32
#define BTn  (Bn*Tn)          // 131072 positions
#define DTC  0.1f
#define LOG2E 1.4426950408889634f

typedef unsigned long long u64;
typedef ulonglong2 u64x2;

// ---------------- scratch (static device globals; no allocation) ----------------
__device__ float g_xp  [(size_t)BTn*Hn];        //  64 MB
__device__ float g_inp [(size_t)Sn*BTn*Hn];     // 268 MB (pair-interleaved channels)
__device__ float g_itau[(size_t)Sn*BTn*Hn];     // 268 MB (pair-interleaved channels)
__device__ float g_hT  [Sn*Bn*Hn];

// ---------------- packed fp32x2 helpers (Blackwell FFMA2) ----------------
__device__ __forceinline__ void ffma2(u64 &d, u64 a, u64 b) {
    asm("fma.rn.f32x2 %0, %1, %2, %0;" : "+l"(d) : "l"(a), "l"(b));
}
__device__ __forceinline__ void add2(u64 &d, u64 a) {
    asm("add.rn.f32x2 %0, %0, %1;" : "+l"(d) : "l"(a));
}
__device__ __forceinline__ float hsum1(u64 a0) {
    float x0, y0;
    asm("mov.b64 {%0,%1}, %2;" : "=f"(x0), "=f"(y0) : "l"(a0));
    return x0 + y0;
}
__device__ __forceinline__ float hsum2p(u64 a0, u64 a1) {
    add2(a0, a1);
    return hsum1(a0);
}
__device__ __forceinline__ float hsum4(u64 a0, u64 a1, u64 a2, u64 a3) {
    add2(a0, a1); add2(a2, a3); add2(a0, a2);
    return hsum1(a0);
}

// ---------------- fast approx math ----------------
__device__ __forceinline__ float fast_ex2(float x) {
    float r; asm("ex2.approx.f32 %0, %1;" : "=f"(r) : "f"(x)); return r;
}
__device__ __forceinline__ float fast_rcp(float x) {
    float r; asm("rcp.approx.f32 %0, %1;" : "=f"(r) : "f"(x)); return r;
}
__device__ __forceinline__ float fast_sqrt(float x) {
    float r; asm("sqrt.approx.f32 %0, %1;" : "=f"(r) : "f"(x)); return r;
}
// tanh(x) = 1 - 2/(e^{2x}+1)
__device__ __forceinline__ float fast_tanh(float x) {
    float xc = fminf(fmaxf(x, -12.f), 12.f);
    float e  = fast_ex2(xc * (2.f * LOG2E));
    return 1.f - 2.f * fast_rcp(e + 1.f);
}
__device__ __forceinline__ float fast_sigmoid(float z) {
    float zc = fminf(fmaxf(z, -30.f), 30.f);
    return fast_rcp(1.f + fast_ex2(-zc * LOG2E));
}

// channel i -> pair-interleaved slot within a 128-wide row
__device__ __forceinline__ int drive_slot(int i) { return ((i & 63) << 1) | (i >> 6); }

// ============================================================================
// K1: x_proj[pos, i] = x[pos, :32] @ Wp[i, :32] + bp[i]
// ============================================================================
__global__ void __launch_bounds__(128) k_xp(const float* __restrict__ x,
                                            const float* __restrict__ Wp,
                                            const float* __restrict__ bp) {
    const int i  = threadIdx.x;
    const int p0 = blockIdx.x * 32;
    __shared__ __align__(16) float xs[32][INn];

    const float4* src = (const float4*)(x + (size_t)p0 * INn);
    float4* dst = (float4*)&xs[0][0];
    dst[i]       = src[i];
    dst[i + 128] = src[i + 128];

    u64 w[16];
    {
        const u64x2* wq = (const u64x2*)(Wp + (size_t)i * INn);
#pragma unroll
        for (int m = 0; m < 8; m++) { u64x2 v = wq[m]; w[2*m] = v.x; w[2*m+1] = v.y; }
    }
    const float bias = bp[i];
    __syncthreads();

#pragma unroll 4
    for (int p = 0; p < 32; p++) {
        const u64x2* xq = (const u64x2*)&xs[p][0];
        u64 a0 = 0ull, a1 = 0ull, a2 = 0ull, a3 = 0ull;
#pragma unroll
        for (int m = 0; m < 8; m += 2) {
            u64x2 p0v = xq[m], p1v = xq[m+1];
            ffma2(a0, w[2*m],   p0v.x); ffma2(a1, w[2*m+1], p0v.y);
            ffma2(a2, w[2*m+2], p1v.x); ffma2(a3, w[2*m+3], p1v.y);
        }
        g_xp[(size_t)(p0 + p) * Hn + i] = hsum4(a0, a1, a2, a3) + bias;
    }
}

// ============================================================================
// K2: inp drive; stores pair-interleaved: channel i -> slot (i&63)*2+(i>>6)
// ============================================================================
__global__ void __launch_bounds__(128) k_inp(const float* __restrict__ Win_w,
                                             const float* __restrict__ Win_b,
                                             const float* __restrict__ cbias) {
    const int i  = threadIdx.x;
    const int s  = blockIdx.y;
    const int p0 = blockIdx.x * 32;
    __shared__ __align__(16) float xs[32][Hn];

    const float4* src = (const float4*)(g_xp + (size_t)p0 * Hn);
    float4* dst = (float4*)&xs[0][0];
#pragma unroll
    for (int r = i; r < 1024; r += 128) dst[r] = src[r];

    u64 w[64];
    {
        const u64x2* wq = (const u64x2*)(Win_w + ((size_t)s * Hn + i) * Hn);
#pragma unroll
        for (int m = 0; m < 32; m++) { u64x2 v = wq[m]; w[2*m] = v.x; w[2*m+1] = v.y; }
    }
    const float bias = Win_b[s * Hn + i] + cbias[s * Hn + i];
    __syncthreads();

    float* outp = g_inp + ((size_t)s * BTn + p0) * Hn + drive_slot(i);
#pragma unroll 2
    for (int p = 0; p < 32; p++) {
        const u64x2* xq = (const u64x2*)&xs[p][0];
        u64 a0 = 0ull, a1 = 0ull, a2 = 0ull, a3 = 0ull;
#pragma unroll
        for (int m = 0; m < 32; m += 2) {
            u64x2 p0v = xq[m], p1v = xq[m+1];
            ffma2(a0, w[2*m],   p0v.x); ffma2(a1, w[2*m+1], p0v.y);
            ffma2(a2, w[2*m+2], p1v.x); ffma2(a3, w[2*m+3], p1v.y);
        }
        __stwt(outp + (size_t)p * Hn, hsum4(a0, a1, a2, a3) + bias);
    }
}

// ============================================================================
// K3: volatility gate -> itau (pair-interleaved store)
// ============================================================================
__global__ void __launch_bounds__(128) k_itau(const float* __restrict__ v1w,
                                              const float* __restrict__ v1b,
                                              const float* __restrict__ v2w,
                                              const float* __restrict__ v2b,
                                              const float* __restrict__ tau_base) {
    const int i  = threadIdx.x;
    const int s  = blockIdx.y;
    const int p0 = blockIdx.x * 32;
    __shared__ __align__(16) float xs[32][Hn];
    __shared__ __align__(16) float gs[32][HQn];

    const float4* src = (const float4*)(g_xp + (size_t)p0 * Hn);
    float4* dst = (float4*)&xs[0][0];
#pragma unroll
    for (int r = i; r < 1024; r += 128) dst[r] = src[r];
    __syncthreads();

    // ---- stage 1: g = relu(xp @ v1w.T + v1b) ----
    {
        const int q   = i & 31;
        const int grp = i >> 5;
        u64 wv[64];
        const u64x2* wq = (const u64x2*)(v1w + ((size_t)s * HQn + q) * Hn);
#pragma unroll
        for (int m = 0; m < 32; m++) { u64x2 v = wq[m]; wv[2*m] = v.x; wv[2*m+1] = v.y; }
        const float b1 = v1b[s * HQn + q];
#pragma unroll 2
        for (int pp = 0; pp < 8; pp++) {
            const int p = grp * 8 + pp;
            const u64x2* xq = (const u64x2*)&xs[p][0];
            u64 a0 = 0ull, a1 = 0ull, a2 = 0ull, a3 = 0ull;
#pragma unroll
            for (int m = 0; m < 32; m += 2) {
                u64x2 p0v = xq[m], p1v = xq[m+1];
                ffma2(a0, wv[2*m],   p0v.x); ffma2(a1, wv[2*m+1], p0v.y);
                ffma2(a2, wv[2*m+2], p1v.x); ffma2(a3, wv[2*m+3], p1v.y);
            }
            gs[p][q] = fmaxf(hsum4(a0, a1, a2, a3) + b1, 0.f);
        }
    }
    __syncthreads();

    // ---- stage 2: vol -> itau ----
    {
        u64 w2[16];
        const u64x2* wq = (const u64x2*)(v2w + ((size_t)s * Hn + i) * HQn);
#pragma unroll
        for (int m = 0; m < 8; m++) { u64x2 v = wq[m]; w2[2*m] = v.x; w2[2*m+1] = v.y; }
        const float b2 = v2b[s * Hn + i];
        const float tb = tau_base[s * Hn + i];
        float* outp = g_itau + ((size_t)s * BTn + p0) * Hn + drive_slot(i);
#pragma unroll 2
        for (int p = 0; p < 32; p++) {
            const u64x2* gq = (const u64x2*)&gs[p][0];
            u64 a0 = 0ull, a1 = 0ull, a2 = 0ull, a3 = 0ull;
#pragma unroll
            for (int m = 0; m < 8; m += 2) {
                u64x2 p0v = gq[m], p1v = gq[m+1];
                ffma2(a0, w2[2*m],   p0v.x); ffma2(a1, w2[2*m+1], p0v.y);
                ffma2(a2, w2[2*m+2], p1v.x); ffma2(a3, w2[2*m+3], p1v.y);
            }
            const float z   = hsum4(a0, a1, a2, a3) + b2;
            const float vol = fast_sigmoid(z);
            float tau = tb * (0.2f + 1.8f * (1.f - vol));
            tau = fminf(fmaxf(tau, 0.1f), 10.f);
            __stwt(outp + (size_t)p * Hn, 1.f / tau);
        }
    }
}

// ============================================================================
// K4: liquid-cell scan, 2-outputs-per-thread split-K.
// 128 threads/CTA. Thread (warp w, lane l): half = l>>4, cc = w*16 + (l&15).
// Owns output channels cc and cc+64; holds W[cc][half*64..+64) and
// W[cc+64][half*64..+64) in regs (128 floats). Each h value loaded from smem
// serves 2 MACs -> smem return traffic halved vs 1-output layout.
// Partner (l^16, same warp) holds the other K-half: combine via shfl_xor(16).
// Norm: lanes l/l^16 duplicate -> shfl {1,2,4,8} + cross-warp via smem.
// ============================================================================
__global__ void __launch_bounds__(128, 3) k_scan(const float* __restrict__ Wrec) {
    const int bid  = blockIdx.x;
    const int s    = 3 - (bid >> 8);     // heavy scale first (LPT)
    const int b    = bid & 255;
    const int t    = threadIdx.x;
    const int wid  = t >> 5;
    const int lane = t & 31;
    const int half = lane >> 4;                 // K-half
    const int cc   = wid * 16 + (lane & 15);    // 0..63

    __shared__ __align__(16) float h_s[Hn];
    __shared__ __align__(16) float red[4];

    // two half-rows of Wrec in registers
    u64 w1[32], w2[32];
    {
        const u64x2* wq1 = (const u64x2*)(Wrec + ((size_t)s * Hn + cc) * Hn + half * 64);
        const u64x2* wq2 = (const u64x2*)(Wrec + ((size_t)s * Hn + cc + 64) * Hn + half * 64);
#pragma unroll
        for (int m = 0; m < 16; m++) { u64x2 v = wq1[m]; w1[2*m] = v.x; w1[2*m+1] = v.y; }
#pragma unroll
        for (int m = 0; m < 16; m++) { u64x2 v = wq2[m]; w2[2*m] = v.x; w2[2*m+1] = v.y; }
    }

    float h1 = 0.f, h2 = 0.f;
    h_s[t] = 0.f;
    const int nsteps = 3 + 2 * s;
    // drive: pair-interleaved float2 per channel pair (cc, cc+64)
    const float2* inp_ptr  = (const float2*)g_inp  + ((size_t)(s * Bn + b)) * Tn * 64 + cc;
    const float2* itau_ptr = (const float2*)g_itau + ((size_t)(s * Bn + b)) * Tn * 64 + cc;
    __syncthreads();

    float2 inp  = __ldcs(inp_ptr);
    float2 itau = __ldcs(itau_ptr);
    for (int tt = 0; tt < Tn; tt++) {
        const int tn = (tt + 1 < Tn) ? tt + 1 : tt;
        const float2 ninp  = __ldcs(inp_ptr  + (size_t)tn * 64);
        const float2 nitau = __ldcs(itau_ptr + (size_t)tn * 64);

        for (int k = 0; k < nsteps; k++) {
            // partial dots over this thread's 64 h-values for both outputs
            const u64x2* hq = (const u64x2*)(h_s + half * 64);
            u64 a0 = 0ull, a1 = 0ull, b0 = 0ull, b1 = 0ull;
#pragma unroll
            for (int m = 0; m < 16; m++) {
                u64x2 hv = hq[m];
                ffma2(a0, w1[2*m],   hv.x); ffma2(b0, w2[2*m],   hv.x);
                ffma2(a1, w1[2*m+1], hv.y); ffma2(b1, w2[2*m+1], hv.y);
            }
            float p1 = hsum2p(a0, a1);
            float p2 = hsum2p(b0, b1);
            const float z1 = p1 + __shfl_xor_sync(0xffffffffu, p1, 16) + inp.x;
            const float z2 = p2 + __shfl_xor_sync(0xffffffffu, p2, 16) + inp.y;

            const float dh1 = (fast_tanh(z1) - h1) * itau.x;
            const float dh2 = (fast_tanh(z2) - h2) * itau.y;

            // ||dhdt||^2: halves duplicate -> {1,2,4,8} sums 32 channels/warp
            float sq = fmaf(dh1, dh1, dh2 * dh2);
            sq += __shfl_xor_sync(0xffffffffu, sq, 1);
            sq += __shfl_xor_sync(0xffffffffu, sq, 2);
            sq += __shfl_xor_sync(0xffffffffu, sq, 4);
            sq += __shfl_xor_sync(0xffffffffu, sq, 8);
            if (lane == 0) red[wid] = sq;
            __syncthreads();
            const float4 r = *(const float4*)red;
            const float mag = fast_sqrt((r.x + r.y) + (r.z + r.w));
            const float sc  = DTC * fast_rcp(fmaf(0.2f, mag, 1.f));
            h1 = fmaf(sc, dh1, h1);
            h2 = fmaf(sc, dh2, h2);
            if (half == 0) { h_s[cc] = h1; h_s[cc + 64] = h2; }
            __syncthreads();
        }
        inp = ninp; itau = nitau;
    }
    if (half == 0) {
        g_hT[((size_t)(s * Bn + b)) * Hn + cc]      = h1;
        g_hT[((size_t)(s * Bn + b)) * Hn + cc + 64] = h2;
    }
}

// ============================================================================
// K5: projection heads + fusion MLP. One CTA per batch row.
// ============================================================================
__global__ void __launch_bounds__(128) k_head(const float* __restrict__ proj_w,
                                              const float* __restrict__ proj_b,
                                              const float* __restrict__ f1_w,
                                              const float* __restrict__ f1_b,
                                              const float* __restrict__ f2_w,
                                              const float* __restrict__ f2_b,
                                              const float* __restrict__ f3_w,
                                              const float* __restrict__ f3_b,
                                              float* __restrict__ out) {
    const int b = blockIdx.x;
    const int i = threadIdx.x;
    __shared__ float fs[Hn];
    __shared__ float h1s[Hn];
    __shared__ float h2s[64];
    __shared__ float rs[4];

    {
        const int s = i >> 5, q = i & 31;
        const float* hrow = g_hT + (size_t)(s * Bn + b) * Hn;
        const float* pw   = proj_w + (size_t)(s * 32 + q) * Hn;
        float acc = proj_b[s * 32 + q];
#pragma unroll 8
        for (int j = 0; j < Hn; j++) acc += hrow[j] * pw[j];
        fs[i] = acc;
    }
    __syncthreads();

    {
        const float* w1 = f1_w + (size_t)i * Hn;
        float acc = f1_b[i];
#pragma unroll 8
        for (int j = 0; j < Hn; j++) acc += fs[j] * w1[j];
        h1s[i] = fmaxf(acc, 0.f);
    }
    __syncthreads();

    if (i < 64) {
        const float* w2 = f2_w + (size_t)i * Hn;
        float acc = f2_b[i];
#pragma unroll 8
        for (int j = 0; j < Hn; j++) acc += h1s[j] * w2[j];
        h2s[i] = fmaxf(acc, 0.f);
    }
    __syncthreads();

    float pr = (i < 64) ? h2s[i] * f3_w[i] : 0.f;
#pragma unroll
    for (int off = 16; off; off >>= 1) pr += __shfl_xor_sync(0xffffffffu, pr, off);
    if ((i & 31) == 0) rs[i >> 5] = pr;
    __syncthreads();
    if (i == 0) out[b] = rs[0] + rs[1] + f3_b[0];
}

// ============================================================================
extern "C" void kernel_launch(void* const* d_in, const int* in_sizes, int n_in,
                              void* d_out, int out_size) {
    (void)in_sizes; (void)n_in; (void)out_size;
    const float* x        = (const float*)d_in[0];
    const float* Wp       = (const float*)d_in[1];
    const float* bp       = (const float*)d_in[2];
    const float* Wrec     = (const float*)d_in[3];
    const float* Win_w    = (const float*)d_in[4];
    const float* Win_b    = (const float*)d_in[5];
    const float* cbias    = (const float*)d_in[6];
    const float* tau_base = (const float*)d_in[7];
    const float* vg1_w    = (const float*)d_in[8];
    const float* vg1_b    = (const float*)d_in[9];
    const float* vg2_w    = (const float*)d_in[10];
    const float* vg2_b    = (const float*)d_in[11];
    const float* proj_w   = (const float*)d_in[12];
    const float* proj_b   = (const float*)d_in[13];
    const float* f1_w     = (const float*)d_in[14];
    const float* f1_b     = (const float*)d_in[15];
    const float* f2_w     = (const float*)d_in[16];
    const float* f2_b     = (const float*)d_in[17];
    const float* f3_w     = (const float*)d_in[18];
    const float* f3_b     = (const float*)d_in[19];
    float* out = (float*)d_out;

    k_xp  <<<BTn / 32, 128>>>(x, Wp, bp);
    k_inp <<<dim3(BTn / 32, Sn), 128>>>(Win_w, Win_b, cbias);
    k_itau<<<dim3(BTn / 32, Sn), 128>>>(vg1_w, vg1_b, vg2_w, vg2_b, tau_base);
    k_scan<<<Sn * Bn, 128>>>(Wrec);
    k_head<<<Bn, 128>>>(proj_w, proj_b, f1_w, f1_b, f2_w, f2_b, f3_w, f3_b, out);
}